// round 12
// baseline (speedup 1.0000x reference)
#include <cuda_runtime.h>
#include <math.h>
#include <stdint.h>

#define K_CTX 64
#define D_DIM 128
#define C_CAND 256
#define DS 200
#define EPS 1e-8f

// Scratch (device globals; no allocation allowed)
__device__ __align__(16) float g_A[K_CTX * D_DIM];
__device__ __align__(16) float g_AM[K_CTX * D_DIM];

// sB row stride 140 floats (560B, 16B aligned): LDS.128 conflict-free
#define SB_STRIDE 140
#define SB_ROW_BYTES (SB_STRIDE * 4)   // 560
#define SMEM_FLOATS (8192 + K_CTX * SB_STRIDE + 4 * 64 + 2 * 128 + 4 + 4)

__device__ __forceinline__ uint32_t smem_u32(const void* p) {
    return (uint32_t)__cvta_generic_to_shared(p);
}
__device__ __forceinline__ void mbar_init(uint32_t mbar, uint32_t cnt) {
    asm volatile("mbarrier.init.shared.b64 [%0], %1;" :: "r"(mbar), "r"(cnt) : "memory");
}
__device__ __forceinline__ void mbar_expect_tx(uint32_t mbar, uint32_t bytes) {
    asm volatile("mbarrier.arrive.expect_tx.shared.b64 _, [%0], %1;"
                 :: "r"(mbar), "r"(bytes) : "memory");
}
__device__ __forceinline__ void mbar_wait(uint32_t mbar, uint32_t parity) {
    uint32_t done;
    asm volatile(
        "{\n\t.reg .pred p;\n\t"
        "mbarrier.try_wait.parity.acquire.cta.shared::cta.b64 p, [%1], %2;\n\t"
        "selp.b32 %0, 1, 0, p;\n\t}"
        : "=r"(done) : "r"(mbar), "r"(parity) : "memory");
    if (!done) {
        asm volatile(
            "{\n\t.reg .pred P1;\n\t"
            "WAIT_LOOP_%=:\n\t"
            "mbarrier.try_wait.parity.acquire.cta.shared::cta.b64 P1, [%0], %1, 0x989680;\n\t"
            "@P1 bra.uni WAIT_DONE_%=;\n\t"
            "bra.uni WAIT_LOOP_%=;\n\t"
            "WAIT_DONE_%=:\n\t}"
            :: "r"(mbar), "r"(parity) : "memory");
    }
}
__device__ __forceinline__ void bulk_g2s(uint32_t dst_smem, const void* src_gmem,
                                         uint32_t bytes, uint32_t mbar) {
    asm volatile(
        "cp.async.bulk.shared::cluster.global.mbarrier::complete_tx::bytes "
        "[%0], [%1], %2, [%3];"
        :: "r"(dst_smem), "l"(src_gmem), "r"(bytes), "r"(mbar) : "memory");
}
__device__ __forceinline__ float tanh_fast(float x) {
    float y;
    asm("tanh.approx.f32 %0, %1;" : "=f"(y) : "f"(x));
    return y;
}
__device__ __forceinline__ unsigned long long ffma2(unsigned long long a,
                                                    unsigned long long b,
                                                    unsigned long long c) {
    unsigned long long d;
    asm("fma.rn.f32x2 %0, %1, %2, %3;" : "=l"(d) : "l"(a), "l"(b), "l"(c));
    return d;
}
__device__ __forceinline__ float f32x2_hsum(unsigned long long v) {
    float lo = __uint_as_float((unsigned)(v & 0xffffffffull));
    float hi = __uint_as_float((unsigned)(v >> 32));
    return lo + hi;
}

// ---------------------------------------------------------------------------
// Kernel 1: prep — grid 64, block 512. Block k computes A row k and AM row k.
// Signals PDL dependents immediately so cand overlaps with us.
// ---------------------------------------------------------------------------
__global__ __launch_bounds__(512, 2)
void prep_kernel(const float* __restrict__ table,
                 const float* __restrict__ att_mat,
                 const int* __restrict__ t1_ctx) {
    // Let the dependent grid launch right away; its griddepcontrol.wait
    // still blocks until this whole grid's stores are visible.
    asm volatile("griddepcontrol.launch_dependents;" ::: "memory");

    __shared__ float arow[D_DIM];
    __shared__ float part[512];
    const int k   = blockIdx.x;
    const int tid = threadIdx.x;

    if (tid < D_DIM) {
        float a = table[(long long)t1_ctx[k] * D_DIM + tid];
        arow[tid] = a;
        g_A[k * D_DIM + tid] = a;
    }
    __syncthreads();
    {
        const int d = tid & 127;
        const int q = tid >> 7;
        const float* att = att_mat + (q * 32) * D_DIM + d;
        const float* ar  = arow + q * 32;
        float acc = 0.f;
#pragma unroll
        for (int e = 0; e < 32; e++)
            acc = fmaf(ar[e], att[e * D_DIM], acc);
        part[tid] = acc;
    }
    __syncthreads();
    if (tid < D_DIM)
        g_AM[k * D_DIM + tid] = part[tid] + part[D_DIM + tid]
                              + part[2 * D_DIM + tid] + part[3 * D_DIM + tid];
}

// ---------------------------------------------------------------------------
// Kernel 2: main — grid 256 (one block per candidate), block 512, 3/SM.
// Launched with programmatic stream serialization: starts concurrently with
// prep; only the AM bulk-copy issue waits on prep via griddepcontrol.wait.
// ---------------------------------------------------------------------------
__global__ __launch_bounds__(512, 3)
void cand_kernel(const float* __restrict__ table,
                 const float* __restrict__ str_t1,
                 const float* __restrict__ str_t2s,
                 const float* __restrict__ W,     // W_bi[0]: [128,128]
                 const float* __restrict__ b_bi,
                 const int* __restrict__ t2_ctx,
                 float* __restrict__ out) {
    extern __shared__ __align__(16) float sm[];
    float* sAM    = sm;                        // 64*128 (tail scratch too)
    float* sB     = sAM + K_CTX * D_DIM;       // 64*140
    float* rowsum = sB + K_CTX * SB_STRIDE;    // 64
    float* colsum = rowsum + K_CTX;            // 64
    float* rows_w = colsum + K_CTX;            // 64
    float* cols_w = rows_w + K_CTX;            // 64
    float* newA   = cols_w + K_CTX;            // 128
    float* newB   = newA + D_DIM;              // 128
    float* scal   = newB + D_DIM;              // 4
    uint64_t* mbars = (uint64_t*)(scal + 4);   // [0]=gather, [1]=sAM stage

    const int c    = blockIdx.x;
    const int tid  = threadIdx.x;
    const int wid  = tid >> 5;                 // 0..15
    const int lane = tid & 31;
    const uint32_t mbar_g = smem_u32(&mbars[0]);
    const uint32_t mbar_a = smem_u32(&mbars[1]);

    // --- phase 0: init mbarriers + zero accumulators ---
    if (tid == 0) {
        mbar_init(mbar_g, 1);
        mbar_init(mbar_a, 1);
        mbar_expect_tx(mbar_g, K_CTX * D_DIM * 4);
        mbar_expect_tx(mbar_a, K_CTX * D_DIM * 4);
    }
    if (tid < K_CTX) colsum[tid] = 0.f;
    if (tid < 4) scal[tid] = 0.f;
    __syncthreads();   // mbar init visible before complete_tx can land

    // --- phase 1: issue B gathers now (independent of prep) ---
    const int* ctx = t2_ctx + c * K_CTX;
    if (tid < K_CTX) {
        bulk_g2s(smem_u32(sB) + tid * SB_ROW_BYTES,
                 table + (long long)ctx[tid] * D_DIM,
                 D_DIM * 4, mbar_g);
    }

    // --- phase 2: string cosine partials (independent of prep) ---
    {
        float pd = 0.f, p1 = 0.f, p2 = 0.f;
        if (tid < DS) {
            float x1 = str_t1[tid];
            float x2 = str_t2s[c * DS + tid];
            pd = x1 * x2; p1 = x1 * x1; p2 = x2 * x2;
        }
#pragma unroll
        for (int off = 16; off; off >>= 1) {
            pd += __shfl_down_sync(0xffffffffu, pd, off);
            p1 += __shfl_down_sync(0xffffffffu, p1, off);
            p2 += __shfl_down_sync(0xffffffffu, p2, off);
        }
        if (lane == 0 && wid < 7) {
            atomicAdd(&scal[0], pd);
            atomicAdd(&scal[1], p1);
            atomicAdd(&scal[2], p2);
        }
    }

    // --- phase 2b: wait for prep grid, then issue the AM bulk copy ---
    if (tid == 0) {
        asm volatile("griddepcontrol.wait;" ::: "memory");
        asm volatile("fence.proxy.async;" ::: "memory");
        bulk_g2s(smem_u32(sAM), g_AM, K_CTX * D_DIM * 4, mbar_a);
    }

    // --- phase 3: wait both bulk transfers, then block barrier ---
    // (mbar_a wait + bar.sync also orders all threads' later g_A reads
    //  after prep's completion observed by thread 0.)
    mbar_wait(mbar_g, 0);
    mbar_wait(mbar_a, 0);
    __syncthreads();

    // --- phase 4: sim = tanh(AM @ B^T) with packed f32x2 FMAs ---
    // warp w -> k rows 4w..4w+3; lane -> m cols l, l+32.
    {
        const ulonglong2* am0 = (const ulonglong2*)(sAM + (wid * 4 + 0) * D_DIM);
        const ulonglong2* am1 = (const ulonglong2*)(sAM + (wid * 4 + 1) * D_DIM);
        const ulonglong2* am2 = (const ulonglong2*)(sAM + (wid * 4 + 2) * D_DIM);
        const ulonglong2* am3 = (const ulonglong2*)(sAM + (wid * 4 + 3) * D_DIM);
        const ulonglong2* b0p = (const ulonglong2*)(sB + lane * SB_STRIDE);
        const ulonglong2* b1p = (const ulonglong2*)(sB + (lane + 32) * SB_STRIDE);

        unsigned long long acc00 = 0, acc01 = 0;
        unsigned long long acc10 = 0, acc11 = 0;
        unsigned long long acc20 = 0, acc21 = 0;
        unsigned long long acc30 = 0, acc31 = 0;

#pragma unroll 4
        for (int jv = 0; jv < D_DIM / 4; jv++) {
            ulonglong2 a0 = am0[jv];
            ulonglong2 a1 = am1[jv];
            ulonglong2 a2 = am2[jv];
            ulonglong2 a3 = am3[jv];
            ulonglong2 b0 = b0p[jv];
            ulonglong2 b1 = b1p[jv];

            acc00 = ffma2(a0.x, b0.x, acc00); acc00 = ffma2(a0.y, b0.y, acc00);
            acc01 = ffma2(a0.x, b1.x, acc01); acc01 = ffma2(a0.y, b1.y, acc01);
            acc10 = ffma2(a1.x, b0.x, acc10); acc10 = ffma2(a1.y, b0.y, acc10);
            acc11 = ffma2(a1.x, b1.x, acc11); acc11 = ffma2(a1.y, b1.y, acc11);
            acc20 = ffma2(a2.x, b0.x, acc20); acc20 = ffma2(a2.y, b0.y, acc20);
            acc21 = ffma2(a2.x, b1.x, acc21); acc21 = ffma2(a2.y, b1.y, acc21);
            acc30 = ffma2(a3.x, b0.x, acc30); acc30 = ffma2(a3.y, b0.y, acc30);
            acc31 = ffma2(a3.x, b1.x, acc31); acc31 = ffma2(a3.y, b1.y, acc31);
        }

        float s00 = tanh_fast(f32x2_hsum(acc00)), s01 = tanh_fast(f32x2_hsum(acc01));
        float s10 = tanh_fast(f32x2_hsum(acc10)), s11 = tanh_fast(f32x2_hsum(acc11));
        float s20 = tanh_fast(f32x2_hsum(acc20)), s21 = tanh_fast(f32x2_hsum(acc21));
        float s30 = tanh_fast(f32x2_hsum(acc30)), s31 = tanh_fast(f32x2_hsum(acc31));

        float r0 = s00 + s01;
        float r1 = s10 + s11;
        float r2 = s20 + s21;
        float r3 = s30 + s31;
#pragma unroll
        for (int off = 16; off; off >>= 1) {
            r0 += __shfl_xor_sync(0xffffffffu, r0, off);
            r1 += __shfl_xor_sync(0xffffffffu, r1, off);
            r2 += __shfl_xor_sync(0xffffffffu, r2, off);
            r3 += __shfl_xor_sync(0xffffffffu, r3, off);
        }
        if (lane == 0) {
            rowsum[wid * 4 + 0] = r0;
            rowsum[wid * 4 + 1] = r1;
            rowsum[wid * 4 + 2] = r2;
            rowsum[wid * 4 + 3] = r3;
        }
        atomicAdd(&colsum[lane],      s00 + s10 + s20 + s30);
        atomicAdd(&colsum[lane + 32], s01 + s11 + s21 + s31);
    }
    __syncthreads();

    // --- phase 5: softmax over 64: warp 0 -> rows, warp 1 -> cols ---
    if (tid < 64) {
        const float* src = (tid < 32) ? rowsum : colsum;
        float* dst       = (tid < 32) ? rows_w : cols_w;
        int l = tid & 31;
        float v0 = src[l]      * (1.f / 64.f);
        float v1 = src[l + 32] * (1.f / 64.f);
        float mx = fmaxf(v0, v1);
#pragma unroll
        for (int off = 16; off; off >>= 1)
            mx = fmaxf(mx, __shfl_xor_sync(0xffffffffu, mx, off));
        float e0 = __expf(v0 - mx);
        float e1 = __expf(v1 - mx);
        float s = e0 + e1;
#pragma unroll
        for (int off = 16; off; off >>= 1)
            s += __shfl_xor_sync(0xffffffffu, s, off);
        float inv = 1.f / s;
        dst[l]      = e0 * inv;
        dst[l + 32] = e1 * inv;
    }
    __syncthreads();

    // --- phase 6: new_A / new_B with all 512 threads (4-way k partials) ---
    {
        const int d = tid & 127;
        const int q = tid >> 7;            // k range [16q, 16q+16)
        float na = 0.f, nb = 0.f;
        const float* gA = g_A + (q * 16) * D_DIM + d;
        const float* sb = sB + (q * 16) * SB_STRIDE + d;
#pragma unroll
        for (int k = 0; k < 16; k++) {
            na = fmaf(rows_w[q * 16 + k], __ldg(gA + k * D_DIM), na);
            nb = fmaf(cols_w[q * 16 + k], sb[k * SB_STRIDE], nb);
        }
        sAM[tid]       = na;               // sAM free after sim: partial scratch
        sAM[512 + tid] = nb;
    }
    __syncthreads();
    if (tid < D_DIM) {
        newA[tid] = sAM[tid] + sAM[128 + tid] + sAM[256 + tid] + sAM[384 + tid];
        newB[tid] = sAM[512 + tid] + sAM[640 + tid] + sAM[768 + tid] + sAM[896 + tid];
    }
    __syncthreads();

    // --- phase 7: con = newA @ W @ newB + b (4-way d partials) ---
    {
        const int e = tid & 127;
        const int q = tid >> 7;            // d range [32q, 32q+32)
        const float* wp = W + (q * 32) * D_DIM + e;
        const float* ap = newA + q * 32;
        float s1 = 0.f;
#pragma unroll
        for (int d = 0; d < 32; d++)
            s1 = fmaf(ap[d], wp[d * D_DIM], s1);
        sAM[tid] = s1;
    }
    __syncthreads();
    if (tid < D_DIM) {
        float s1 = sAM[tid] + sAM[128 + tid] + sAM[256 + tid] + sAM[384 + tid];
        float pc = s1 * newB[tid];
#pragma unroll
        for (int off = 16; off; off >>= 1)
            pc += __shfl_down_sync(0xffffffffu, pc, off);
        if (lane == 0) atomicAdd(&scal[3], pc);
    }
    __syncthreads();

    if (tid == 0) {
        float n1 = fmaxf(sqrtf(scal[1]), EPS);
        float n2 = fmaxf(sqrtf(scal[2]), EPS);
        float str_score = scal[0] / (n1 * n2);
        float con_score = scal[3] + b_bi[0];
        out[c] = 0.5f * str_score + 0.5f * con_score;
    }
}

// ---------------------------------------------------------------------------
extern "C" void kernel_launch(void* const* d_in, const int* in_sizes, int n_in,
                              void* d_out, int out_size) {
    const float* table   = (const float*)d_in[0];
    const float* str_t1  = (const float*)d_in[1];
    const float* str_t2s = (const float*)d_in[2];
    const float* att_mat = (const float*)d_in[3];
    const float* W_bi    = (const float*)d_in[4];
    const float* b_bi    = (const float*)d_in[5];
    const int*   t1_ctx  = (const int*)d_in[6];
    const int*   t2_ctx  = (const int*)d_in[7];
    float* out = (float*)d_out;

    cudaFuncSetAttribute(cand_kernel,
                         cudaFuncAttributeMaxDynamicSharedMemorySize,
                         SMEM_FLOATS * sizeof(float));

    prep_kernel<<<K_CTX, 512>>>(table, att_mat, t1_ctx);

    // PDL launch: cand starts while prep runs; only its AM copy waits.
    cudaLaunchConfig_t cfg = {};
    cfg.gridDim = dim3(C_CAND, 1, 1);
    cfg.blockDim = dim3(512, 1, 1);
    cfg.dynamicSmemBytes = SMEM_FLOATS * sizeof(float);
    cudaLaunchAttribute attrs[1];
    attrs[0].id = cudaLaunchAttributeProgrammaticStreamSerialization;
    attrs[0].val.programmaticStreamSerializationAllowed = 1;
    cfg.attrs = attrs;
    cfg.numAttrs = 1;
    cudaLaunchKernelEx(&cfg, cand_kernel,
                       table, str_t1, str_t2s, W_bi, b_bi, t2_ctx, out);
}

// round 13
// speedup vs baseline: 1.2912x; 1.2912x over previous
#include <cuda_runtime.h>
#include <math.h>
#include <stdint.h>

#define K_CTX 64
#define D_DIM 128
#define C_CAND 256
#define DS 200
#define EPS 1e-8f

// Scratch (device globals; no allocation allowed)
__device__ __align__(16) float g_A[K_CTX * D_DIM];
__device__ __align__(16) float g_AM[K_CTX * D_DIM];

// sB row stride 140 floats (560B, 16B aligned): LDS.128 conflict-free
#define SB_STRIDE 140
#define SB_ROW_BYTES (SB_STRIDE * 4)   // 560
// sAM(8192) sB(8960) colsumP(1024) rowsum(64) rows_w(64) cols_w(64)
// newA(128) newB(128) scal(4) mbars(4)
#define SMEM_FLOATS (8192 + K_CTX * SB_STRIDE + 1024 + 64 + 64 + 64 + 128 + 128 + 4 + 4)

__device__ __forceinline__ uint32_t smem_u32(const void* p) {
    return (uint32_t)__cvta_generic_to_shared(p);
}
__device__ __forceinline__ void mbar_init(uint32_t mbar, uint32_t cnt) {
    asm volatile("mbarrier.init.shared.b64 [%0], %1;" :: "r"(mbar), "r"(cnt) : "memory");
}
__device__ __forceinline__ void mbar_expect_tx(uint32_t mbar, uint32_t bytes) {
    asm volatile("mbarrier.arrive.expect_tx.shared.b64 _, [%0], %1;"
                 :: "r"(mbar), "r"(bytes) : "memory");
}
__device__ __forceinline__ void mbar_wait(uint32_t mbar, uint32_t parity) {
    uint32_t done;
    asm volatile(
        "{\n\t.reg .pred p;\n\t"
        "mbarrier.try_wait.parity.acquire.cta.shared::cta.b64 p, [%1], %2;\n\t"
        "selp.b32 %0, 1, 0, p;\n\t}"
        : "=r"(done) : "r"(mbar), "r"(parity) : "memory");
    if (!done) {
        asm volatile(
            "{\n\t.reg .pred P1;\n\t"
            "WAIT_LOOP_%=:\n\t"
            "mbarrier.try_wait.parity.acquire.cta.shared::cta.b64 P1, [%0], %1, 0x989680;\n\t"
            "@P1 bra.uni WAIT_DONE_%=;\n\t"
            "bra.uni WAIT_LOOP_%=;\n\t"
            "WAIT_DONE_%=:\n\t}"
            :: "r"(mbar), "r"(parity) : "memory");
    }
}
__device__ __forceinline__ void bulk_g2s(uint32_t dst_smem, const void* src_gmem,
                                         uint32_t bytes, uint32_t mbar) {
    asm volatile(
        "cp.async.bulk.shared::cluster.global.mbarrier::complete_tx::bytes "
        "[%0], [%1], %2, [%3];"
        :: "r"(dst_smem), "l"(src_gmem), "r"(bytes), "r"(mbar) : "memory");
}
__device__ __forceinline__ float tanh_fast(float x) {
    float y;
    asm("tanh.approx.f32 %0, %1;" : "=f"(y) : "f"(x));
    return y;
}
__device__ __forceinline__ unsigned long long ffma2(unsigned long long a,
                                                    unsigned long long b,
                                                    unsigned long long c) {
    unsigned long long d;
    asm("fma.rn.f32x2 %0, %1, %2, %3;" : "=l"(d) : "l"(a), "l"(b), "l"(c));
    return d;
}
__device__ __forceinline__ float f32x2_hsum(unsigned long long v) {
    float lo = __uint_as_float((unsigned)(v & 0xffffffffull));
    float hi = __uint_as_float((unsigned)(v >> 32));
    return lo + hi;
}

// ---------------------------------------------------------------------------
// Kernel 1: prep — grid 64, block 512. Block k computes A row k and AM row k.
// ---------------------------------------------------------------------------
__global__ __launch_bounds__(512, 2)
void prep_kernel(const float* __restrict__ table,
                 const float* __restrict__ att_mat,
                 const int* __restrict__ t1_ctx) {
    __shared__ float arow[D_DIM];
    __shared__ float part[512];
    const int k   = blockIdx.x;
    const int tid = threadIdx.x;

    if (tid < D_DIM) {
        float a = table[(long long)t1_ctx[k] * D_DIM + tid];
        arow[tid] = a;
        g_A[k * D_DIM + tid] = a;
    }
    __syncthreads();
    {
        const int d = tid & 127;
        const int q = tid >> 7;
        const float* att = att_mat + (q * 32) * D_DIM + d;
        const float* ar  = arow + q * 32;
        float acc = 0.f;
#pragma unroll
        for (int e = 0; e < 32; e++)
            acc = fmaf(ar[e], att[e * D_DIM], acc);
        part[tid] = acc;
    }
    __syncthreads();
    if (tid < D_DIM)
        g_AM[k * D_DIM + tid] = part[tid] + part[D_DIM + tid]
                              + part[2 * D_DIM + tid] + part[3 * D_DIM + tid];
}

// ---------------------------------------------------------------------------
// Kernel 2: main — grid 256 (one block per candidate), block 512, 3/SM.
// Graph edge guarantees g_A/g_AM ready; all async copies issued at phase 0.
// colsum via per-warp partial stores (no shared atomics on the LSU path).
// ---------------------------------------------------------------------------
__global__ __launch_bounds__(512, 3)
void cand_kernel(const float* __restrict__ table,
                 const float* __restrict__ str_t1,
                 const float* __restrict__ str_t2s,
                 const float* __restrict__ W,     // W_bi[0]: [128,128]
                 const float* __restrict__ b_bi,
                 const int* __restrict__ t2_ctx,
                 float* __restrict__ out) {
    extern __shared__ __align__(16) float sm[];
    float* sAM     = sm;                        // 64*128 (tail scratch too)
    float* sB      = sAM + K_CTX * D_DIM;       // 64*140
    float* colsumP = sB + K_CTX * SB_STRIDE;    // [16][64] per-warp partials
    float* rowsum  = colsumP + 1024;            // 64
    float* rows_w  = rowsum + K_CTX;            // 64
    float* cols_w  = rows_w + K_CTX;            // 64
    float* newA    = cols_w + K_CTX;            // 128
    float* newB    = newA + D_DIM;              // 128
    float* scal    = newB + D_DIM;              // 4
    uint64_t* mbars = (uint64_t*)(scal + 4);    // [0]=gather, [1]=sAM stage

    const int c    = blockIdx.x;
    const int tid  = threadIdx.x;
    const int wid  = tid >> 5;                 // 0..15
    const int lane = tid & 31;
    const uint32_t mbar_g = smem_u32(&mbars[0]);
    const uint32_t mbar_a = smem_u32(&mbars[1]);

    // --- phase 0: init mbarriers + zero accumulators ---
    if (tid == 0) {
        mbar_init(mbar_g, 1);
        mbar_init(mbar_a, 1);
        mbar_expect_tx(mbar_g, K_CTX * D_DIM * 4);
        mbar_expect_tx(mbar_a, K_CTX * D_DIM * 4);
    }
    if (tid < 4) scal[tid] = 0.f;
    __syncthreads();   // mbar init visible before complete_tx can land

    // --- phase 1: issue ALL async copies up front ---
    const int* ctx = t2_ctx + c * K_CTX;
    if (tid < K_CTX) {
        bulk_g2s(smem_u32(sB) + tid * SB_ROW_BYTES,
                 table + (long long)ctx[tid] * D_DIM,
                 D_DIM * 4, mbar_g);
    } else if (tid == K_CTX) {
        bulk_g2s(smem_u32(sAM), g_AM, K_CTX * D_DIM * 4, mbar_a);
    }

    // --- phase 2: string cosine partials (hide transfer latency) ---
    {
        float pd = 0.f, p1 = 0.f, p2 = 0.f;
        if (tid < DS) {
            float x1 = str_t1[tid];
            float x2 = str_t2s[c * DS + tid];
            pd = x1 * x2; p1 = x1 * x1; p2 = x2 * x2;
        }
#pragma unroll
        for (int off = 16; off; off >>= 1) {
            pd += __shfl_down_sync(0xffffffffu, pd, off);
            p1 += __shfl_down_sync(0xffffffffu, p1, off);
            p2 += __shfl_down_sync(0xffffffffu, p2, off);
        }
        if (lane == 0 && wid < 7) {
            atomicAdd(&scal[0], pd);
            atomicAdd(&scal[1], p1);
            atomicAdd(&scal[2], p2);
        }
    }

    // --- phase 3: wait both bulk transfers, then block barrier ---
    mbar_wait(mbar_g, 0);
    mbar_wait(mbar_a, 0);
    __syncthreads();

    // --- phase 4: sim = tanh(AM @ B^T) with packed f32x2 FMAs ---
    // warp w -> k rows 4w..4w+3; lane -> m cols l, l+32.
    {
        const ulonglong2* am0 = (const ulonglong2*)(sAM + (wid * 4 + 0) * D_DIM);
        const ulonglong2* am1 = (const ulonglong2*)(sAM + (wid * 4 + 1) * D_DIM);
        const ulonglong2* am2 = (const ulonglong2*)(sAM + (wid * 4 + 2) * D_DIM);
        const ulonglong2* am3 = (const ulonglong2*)(sAM + (wid * 4 + 3) * D_DIM);
        const ulonglong2* b0p = (const ulonglong2*)(sB + lane * SB_STRIDE);
        const ulonglong2* b1p = (const ulonglong2*)(sB + (lane + 32) * SB_STRIDE);

        unsigned long long acc00 = 0, acc01 = 0;
        unsigned long long acc10 = 0, acc11 = 0;
        unsigned long long acc20 = 0, acc21 = 0;
        unsigned long long acc30 = 0, acc31 = 0;

#pragma unroll 4
        for (int jv = 0; jv < D_DIM / 4; jv++) {
            ulonglong2 a0 = am0[jv];
            ulonglong2 a1 = am1[jv];
            ulonglong2 a2 = am2[jv];
            ulonglong2 a3 = am3[jv];
            ulonglong2 b0 = b0p[jv];
            ulonglong2 b1 = b1p[jv];

            acc00 = ffma2(a0.x, b0.x, acc00); acc00 = ffma2(a0.y, b0.y, acc00);
            acc01 = ffma2(a0.x, b1.x, acc01); acc01 = ffma2(a0.y, b1.y, acc01);
            acc10 = ffma2(a1.x, b0.x, acc10); acc10 = ffma2(a1.y, b0.y, acc10);
            acc11 = ffma2(a1.x, b1.x, acc11); acc11 = ffma2(a1.y, b1.y, acc11);
            acc20 = ffma2(a2.x, b0.x, acc20); acc20 = ffma2(a2.y, b0.y, acc20);
            acc21 = ffma2(a2.x, b1.x, acc21); acc21 = ffma2(a2.y, b1.y, acc21);
            acc30 = ffma2(a3.x, b0.x, acc30); acc30 = ffma2(a3.y, b0.y, acc30);
            acc31 = ffma2(a3.x, b1.x, acc31); acc31 = ffma2(a3.y, b1.y, acc31);
        }

        float s00 = tanh_fast(f32x2_hsum(acc00)), s01 = tanh_fast(f32x2_hsum(acc01));
        float s10 = tanh_fast(f32x2_hsum(acc10)), s11 = tanh_fast(f32x2_hsum(acc11));
        float s20 = tanh_fast(f32x2_hsum(acc20)), s21 = tanh_fast(f32x2_hsum(acc21));
        float s30 = tanh_fast(f32x2_hsum(acc30)), s31 = tanh_fast(f32x2_hsum(acc31));

        float r0 = s00 + s01;
        float r1 = s10 + s11;
        float r2 = s20 + s21;
        float r3 = s30 + s31;
#pragma unroll
        for (int off = 16; off; off >>= 1) {
            r0 += __shfl_xor_sync(0xffffffffu, r0, off);
            r1 += __shfl_xor_sync(0xffffffffu, r1, off);
            r2 += __shfl_xor_sync(0xffffffffu, r2, off);
            r3 += __shfl_xor_sync(0xffffffffu, r3, off);
        }
        if (lane == 0) {
            rowsum[wid * 4 + 0] = r0;
            rowsum[wid * 4 + 1] = r1;
            rowsum[wid * 4 + 2] = r2;
            rowsum[wid * 4 + 3] = r3;
        }
        // colsum partials: plain STS, conflict-free (no ATOMS on the LSU path)
        colsumP[wid * 64 + lane]      = s00 + s10 + s20 + s30;
        colsumP[wid * 64 + lane + 32] = s01 + s11 + s21 + s31;
    }
    __syncthreads();

    // --- phase 5: softmax over 64: warp 0 -> rows, warp 1 -> cols (+16-way sum)
    if (tid < 64) {
        int l = tid & 31;
        float v0, v1;
        if (tid < 32) {
            v0 = rowsum[l];
            v1 = rowsum[l + 32];
        } else {
            float c0 = 0.f, c1 = 0.f;
#pragma unroll
            for (int w = 0; w < 16; w++) {
                c0 += colsumP[w * 64 + l];
                c1 += colsumP[w * 64 + l + 32];
            }
            v0 = c0; v1 = c1;
        }
        float* dst = (tid < 32) ? rows_w : cols_w;
        v0 *= (1.f / 64.f);
        v1 *= (1.f / 64.f);
        float mx = fmaxf(v0, v1);
#pragma unroll
        for (int off = 16; off; off >>= 1)
            mx = fmaxf(mx, __shfl_xor_sync(0xffffffffu, mx, off));
        float e0 = __expf(v0 - mx);
        float e1 = __expf(v1 - mx);
        float s = e0 + e1;
#pragma unroll
        for (int off = 16; off; off >>= 1)
            s += __shfl_xor_sync(0xffffffffu, s, off);
        float inv = 1.f / s;
        dst[l]      = e0 * inv;
        dst[l + 32] = e1 * inv;
    }
    __syncthreads();

    // --- phase 6: new_A / new_B with all 512 threads (4-way k partials) ---
    {
        const int d = tid & 127;
        const int q = tid >> 7;            // k range [16q, 16q+16)
        float na = 0.f, nb = 0.f;
        const float* gA = g_A + (q * 16) * D_DIM + d;
        const float* sb = sB + (q * 16) * SB_STRIDE + d;
#pragma unroll
        for (int k = 0; k < 16; k++) {
            na = fmaf(rows_w[q * 16 + k], __ldg(gA + k * D_DIM), na);
            nb = fmaf(cols_w[q * 16 + k], sb[k * SB_STRIDE], nb);
        }
        sAM[tid]       = na;               // sAM free after sim: partial scratch
        sAM[512 + tid] = nb;
    }
    __syncthreads();
    if (tid < D_DIM) {
        newA[tid] = sAM[tid] + sAM[128 + tid] + sAM[256 + tid] + sAM[384 + tid];
        newB[tid] = sAM[512 + tid] + sAM[640 + tid] + sAM[768 + tid] + sAM[896 + tid];
    }
    __syncthreads();

    // --- phase 7: con = newA @ W @ newB + b (4-way d partials) ---
    {
        const int e = tid & 127;
        const int q = tid >> 7;            // d range [32q, 32q+32)
        const float* wp = W + (q * 32) * D_DIM + e;
        const float* ap = newA + q * 32;
        float s1 = 0.f;
#pragma unroll
        for (int d = 0; d < 32; d++)
            s1 = fmaf(ap[d], wp[d * D_DIM], s1);
        sAM[tid] = s1;
    }
    __syncthreads();
    if (tid < D_DIM) {
        float s1 = sAM[tid] + sAM[128 + tid] + sAM[256 + tid] + sAM[384 + tid];
        float pc = s1 * newB[tid];
#pragma unroll
        for (int off = 16; off; off >>= 1)
            pc += __shfl_down_sync(0xffffffffu, pc, off);
        if (lane == 0) atomicAdd(&scal[3], pc);
    }
    __syncthreads();

    if (tid == 0) {
        float n1 = fmaxf(sqrtf(scal[1]), EPS);
        float n2 = fmaxf(sqrtf(scal[2]), EPS);
        float str_score = scal[0] / (n1 * n2);
        float con_score = scal[3] + b_bi[0];
        out[c] = 0.5f * str_score + 0.5f * con_score;
    }
}

// ---------------------------------------------------------------------------
extern "C" void kernel_launch(void* const* d_in, const int* in_sizes, int n_in,
                              void* d_out, int out_size) {
    const float* table   = (const float*)d_in[0];
    const float* str_t1  = (const float*)d_in[1];
    const float* str_t2s = (const float*)d_in[2];
    const float* att_mat = (const float*)d_in[3];
    const float* W_bi    = (const float*)d_in[4];
    const float* b_bi    = (const float*)d_in[5];
    const int*   t1_ctx  = (const int*)d_in[6];
    const int*   t2_ctx  = (const int*)d_in[7];
    float* out = (float*)d_out;

    cudaFuncSetAttribute(cand_kernel,
                         cudaFuncAttributeMaxDynamicSharedMemorySize,
                         SMEM_FLOATS * sizeof(float));

    prep_kernel<<<K_CTX, 512>>>(table, att_mat, t1_ctx);
    cand_kernel<<<C_CAND, 512, SMEM_FLOATS * sizeof(float)>>>(
        table, str_t1, str_t2s, W_bi, b_bi, t2_ctx, out);
}

// round 14
// speedup vs baseline: 1.8294x; 1.4168x over previous
#include <cuda_runtime.h>
#include <math.h>
#include <stdint.h>

#define K_CTX 64
#define D_DIM 128
#define C_CAND 256
#define DS 200
#define EPS 1e-8f

// Padded row stride: 132 floats (528B, 16B-aligned). Fragment loads at
// word (row*132 + col) -> bank (row*4+col)%32: conflict-free for all frags.
#define PAD_STRIDE 132
#define ROW_BYTES (PAD_STRIDE * 4)      // 528
#define AM_FLOATS (K_CTX * PAD_STRIDE)  // 8448

// Scratch (device globals; zero-init .bss)
__device__ __align__(16) float g_A[K_CTX * D_DIM];      // flat fp32 (tail use)
__device__ __align__(16) float g_AM[AM_FLOATS];         // padded, tf32-rounded

// smem: sAM(8448) sB(8448) rowP(256) colP(256) rows_w(64) cols_w(64)
//       newA(128) newB(128) scal(4) mbars(4)
#define SMEM_FLOATS (AM_FLOATS + AM_FLOATS + 256 + 256 + 64 + 64 + 128 + 128 + 4 + 4)

__device__ __forceinline__ uint32_t smem_u32(const void* p) {
    return (uint32_t)__cvta_generic_to_shared(p);
}
__device__ __forceinline__ void mbar_init(uint32_t mbar, uint32_t cnt) {
    asm volatile("mbarrier.init.shared.b64 [%0], %1;" :: "r"(mbar), "r"(cnt) : "memory");
}
__device__ __forceinline__ void mbar_expect_tx(uint32_t mbar, uint32_t bytes) {
    asm volatile("mbarrier.arrive.expect_tx.shared.b64 _, [%0], %1;"
                 :: "r"(mbar), "r"(bytes) : "memory");
}
__device__ __forceinline__ void mbar_wait(uint32_t mbar, uint32_t parity) {
    uint32_t done;
    asm volatile(
        "{\n\t.reg .pred p;\n\t"
        "mbarrier.try_wait.parity.acquire.cta.shared::cta.b64 p, [%1], %2;\n\t"
        "selp.b32 %0, 1, 0, p;\n\t}"
        : "=r"(done) : "r"(mbar), "r"(parity) : "memory");
    if (!done) {
        asm volatile(
            "{\n\t.reg .pred P1;\n\t"
            "WAIT_LOOP_%=:\n\t"
            "mbarrier.try_wait.parity.acquire.cta.shared::cta.b64 P1, [%0], %1, 0x989680;\n\t"
            "@P1 bra.uni WAIT_DONE_%=;\n\t"
            "bra.uni WAIT_LOOP_%=;\n\t"
            "WAIT_DONE_%=:\n\t}"
            :: "r"(mbar), "r"(parity) : "memory");
    }
}
__device__ __forceinline__ void bulk_g2s(uint32_t dst_smem, const void* src_gmem,
                                         uint32_t bytes, uint32_t mbar) {
    asm volatile(
        "cp.async.bulk.shared::cluster.global.mbarrier::complete_tx::bytes "
        "[%0], [%1], %2, [%3];"
        :: "r"(dst_smem), "l"(src_gmem), "r"(bytes), "r"(mbar) : "memory");
}
__device__ __forceinline__ float tanh_fast(float x) {
    float y;
    asm("tanh.approx.f32 %0, %1;" : "=f"(y) : "f"(x));
    return y;
}
__device__ __forceinline__ uint32_t to_tf32(float x) {
    uint32_t y;
    asm("cvt.rna.tf32.f32 %0, %1;" : "=r"(y) : "f"(x));
    return y;
}
// m16n8k8 tf32 MMA, fp32 accumulate (HMMA path on sm_103a)
__device__ __forceinline__ void mma_tf32(float* c, uint32_t a0, uint32_t a1,
                                         uint32_t a2, uint32_t a3,
                                         uint32_t b0, uint32_t b1) {
    asm volatile(
        "mma.sync.aligned.m16n8k8.row.col.f32.tf32.tf32.f32 "
        "{%0,%1,%2,%3}, {%4,%5,%6,%7}, {%8,%9}, {%0,%1,%2,%3};"
        : "+f"(c[0]), "+f"(c[1]), "+f"(c[2]), "+f"(c[3])
        : "r"(a0), "r"(a1), "r"(a2), "r"(a3), "r"(b0), "r"(b1));
}

// ---------------------------------------------------------------------------
// Kernel 1: prep — grid 64, block 512. Block k: A row k (flat fp32) and
// AM row k (padded stride 132, tf32-rounded) so cand's MMA loads it directly.
// ---------------------------------------------------------------------------
__global__ __launch_bounds__(512, 2)
void prep_kernel(const float* __restrict__ table,
                 const float* __restrict__ att_mat,
                 const int* __restrict__ t1_ctx) {
    __shared__ float arow[D_DIM];
    __shared__ float part[512];
    const int k   = blockIdx.x;
    const int tid = threadIdx.x;

    if (tid < D_DIM) {
        float a = table[(long long)t1_ctx[k] * D_DIM + tid];
        arow[tid] = a;
        g_A[k * D_DIM + tid] = a;
    }
    __syncthreads();
    {
        const int d = tid & 127;
        const int q = tid >> 7;
        const float* att = att_mat + (q * 32) * D_DIM + d;
        const float* ar  = arow + q * 32;
        float acc = 0.f;
#pragma unroll
        for (int e = 0; e < 32; e++)
            acc = fmaf(ar[e], att[e * D_DIM], acc);
        part[tid] = acc;
    }
    __syncthreads();
    if (tid < D_DIM) {
        float v = part[tid] + part[D_DIM + tid]
                + part[2 * D_DIM + tid] + part[3 * D_DIM + tid];
        g_AM[k * PAD_STRIDE + tid] = __uint_as_float(to_tf32(v));
    }
}

// ---------------------------------------------------------------------------
// Kernel 2: main — grid 256, block 512, 3/SM. sim via tensor-core tf32 MMA.
// ---------------------------------------------------------------------------
__global__ __launch_bounds__(512, 3)
void cand_kernel(const float* __restrict__ table,
                 const float* __restrict__ str_t1,
                 const float* __restrict__ str_t2s,
                 const float* __restrict__ W,     // W_bi[0]: [128,128]
                 const float* __restrict__ b_bi,
                 const int* __restrict__ t2_ctx,
                 float* __restrict__ out) {
    extern __shared__ __align__(16) float sm[];
    float* sAM    = sm;                        // [64][132] tf32 AM (+scratch)
    float* sB     = sAM + AM_FLOATS;           // [64][132] fp32 B
    float* rowP   = sB + AM_FLOATS;            // [4][64] per-N-group row partials
    float* colP   = rowP + 256;                // [4][64] per-M-tile col partials
    float* rows_w = colP + 256;                // 64
    float* cols_w = rows_w + K_CTX;            // 64
    float* newA   = cols_w + K_CTX;            // 128
    float* newB   = newA + D_DIM;              // 128
    float* scal   = newB + D_DIM;              // 4
    uint64_t* mbars = (uint64_t*)(scal + 4);   // [0]=gather, [1]=AM stage

    const int c    = blockIdx.x;
    const int tid  = threadIdx.x;
    const int wid  = tid >> 5;                 // 0..15
    const int lane = tid & 31;
    const uint32_t mbar_g = smem_u32(&mbars[0]);
    const uint32_t mbar_a = smem_u32(&mbars[1]);

    // --- phase 0: init mbarriers + zero accumulators ---
    if (tid == 0) {
        mbar_init(mbar_g, 1);
        mbar_init(mbar_a, 1);
        mbar_expect_tx(mbar_g, K_CTX * D_DIM * 4);   // 64 x 512B rows
        mbar_expect_tx(mbar_a, AM_FLOATS * 4);       // padded AM block
    }
    if (tid < 4) scal[tid] = 0.f;
    __syncthreads();

    // --- phase 1: issue all async copies (graph edge guarantees g_AM) ---
    const int* ctx = t2_ctx + c * K_CTX;
    if (tid < K_CTX) {
        bulk_g2s(smem_u32(sB) + tid * ROW_BYTES,
                 table + (long long)ctx[tid] * D_DIM,
                 D_DIM * 4, mbar_g);
    } else if (tid == K_CTX) {
        bulk_g2s(smem_u32(sAM), g_AM, AM_FLOATS * 4, mbar_a);
    }

    // --- phase 2: string cosine partials ---
    {
        float pd = 0.f, p1 = 0.f, p2 = 0.f;
        if (tid < DS) {
            float x1 = str_t1[tid];
            float x2 = str_t2s[c * DS + tid];
            pd = x1 * x2; p1 = x1 * x1; p2 = x2 * x2;
        }
#pragma unroll
        for (int off = 16; off; off >>= 1) {
            pd += __shfl_down_sync(0xffffffffu, pd, off);
            p1 += __shfl_down_sync(0xffffffffu, p1, off);
            p2 += __shfl_down_sync(0xffffffffu, p2, off);
        }
        if (lane == 0 && wid < 7) {
            atomicAdd(&scal[0], pd);
            atomicAdd(&scal[1], p1);
            atomicAdd(&scal[2], p2);
        }
    }

    // --- phase 3: wait transfers ---
    mbar_wait(mbar_g, 0);
    mbar_wait(mbar_a, 0);
    __syncthreads();

    // --- phase 4: sim = tanh(AM @ B^T) via m16n8k8 tf32 MMA ---
    // warp w: M-tile mt = w&3 (sim-k rows 16mt..16mt+15),
    //         N-group g = w>>2 (sim-m cols 16g..16g+15, two 8-col tiles).
    {
        const int mt = wid & 3;
        const int g  = wid >> 2;
        const int q  = lane >> 2;   // 0..7
        const int r  = lane & 3;    // 0..3
        const float* Ab  = sAM + mt * 16 * PAD_STRIDE;
        const float* Bb0 = sB + (g * 16) * PAD_STRIDE;
        const float* Bb1 = Bb0 + 8 * PAD_STRIDE;

        float c0[4] = {0.f, 0.f, 0.f, 0.f};
        float c1[4] = {0.f, 0.f, 0.f, 0.f};

#pragma unroll
        for (int ks = 0; ks < 16; ks++) {
            const int kb = ks * 8;
            // A frag (tf32-rounded fp32 bits, pre-converted in prep)
            uint32_t a0 = __float_as_uint(Ab[q * PAD_STRIDE + kb + r]);
            uint32_t a1 = __float_as_uint(Ab[(q + 8) * PAD_STRIDE + kb + r]);
            uint32_t a2 = __float_as_uint(Ab[q * PAD_STRIDE + kb + r + 4]);
            uint32_t a3 = __float_as_uint(Ab[(q + 8) * PAD_STRIDE + kb + r + 4]);
            // B frags (raw fp32 -> tf32 round)
            uint32_t b00 = to_tf32(Bb0[q * PAD_STRIDE + kb + r]);
            uint32_t b01 = to_tf32(Bb0[q * PAD_STRIDE + kb + r + 4]);
            uint32_t b10 = to_tf32(Bb1[q * PAD_STRIDE + kb + r]);
            uint32_t b11 = to_tf32(Bb1[q * PAD_STRIDE + kb + r + 4]);

            mma_tf32(c0, a0, a1, a2, a3, b00, b01);
            mma_tf32(c1, a0, a1, a2, a3, b10, b11);
        }

        // tanh on the 8 accumulators (C frag: rows 16mt+q, 16mt+q+8;
        // cols tile0: 16g+2r, +1; tile1: 16g+8+2r, +1)
        float d00 = tanh_fast(c0[0]), d01 = tanh_fast(c0[1]);
        float d02 = tanh_fast(c0[2]), d03 = tanh_fast(c0[3]);
        float e00 = tanh_fast(c1[0]), e01 = tanh_fast(c1[1]);
        float e02 = tanh_fast(c1[2]), e03 = tanh_fast(c1[3]);

        // row partials (sum over this warp's 16 m-cols): reduce over r
        float rp1 = d00 + d01 + e00 + e01;   // row 16mt+q
        float rp2 = d02 + d03 + e02 + e03;   // row 16mt+q+8
#pragma unroll
        for (int off = 1; off <= 2; off <<= 1) {
            rp1 += __shfl_xor_sync(0xffffffffu, rp1, off);
            rp2 += __shfl_xor_sync(0xffffffffu, rp2, off);
        }
        if (r == 0) {
            rowP[g * 64 + mt * 16 + q]     = rp1;
            rowP[g * 64 + mt * 16 + q + 8] = rp2;
        }

        // col partials (sum over this warp's 16 k-rows): reduce over q
        float cp0 = d00 + d02;   // col 16g+2r
        float cp1 = d01 + d03;   // col 16g+2r+1
        float cp2 = e00 + e02;   // col 16g+8+2r
        float cp3 = e01 + e03;   // col 16g+8+2r+1
#pragma unroll
        for (int off = 4; off <= 16; off <<= 1) {
            cp0 += __shfl_xor_sync(0xffffffffu, cp0, off);
            cp1 += __shfl_xor_sync(0xffffffffu, cp1, off);
            cp2 += __shfl_xor_sync(0xffffffffu, cp2, off);
            cp3 += __shfl_xor_sync(0xffffffffu, cp3, off);
        }
        if (q == 0) {
            colP[mt * 64 + g * 16 + 2 * r]     = cp0;
            colP[mt * 64 + g * 16 + 2 * r + 1] = cp1;
            colP[mt * 64 + g * 16 + 8 + 2 * r]     = cp2;
            colP[mt * 64 + g * 16 + 8 + 2 * r + 1] = cp3;
        }
    }
    __syncthreads();

    // --- phase 5: softmax over 64 (warp 0 rows, warp 1 cols; fold 4 partials)
    if (tid < 64) {
        int l = tid & 31;
        const float* P = (tid < 32) ? rowP : colP;
        float* dst     = (tid < 32) ? rows_w : cols_w;
        float v0 = P[l]      + P[64 + l]      + P[128 + l]      + P[192 + l];
        float v1 = P[l + 32] + P[64 + l + 32] + P[128 + l + 32] + P[192 + l + 32];
        v0 *= (1.f / 64.f);
        v1 *= (1.f / 64.f);
        float mx = fmaxf(v0, v1);
#pragma unroll
        for (int off = 16; off; off >>= 1)
            mx = fmaxf(mx, __shfl_xor_sync(0xffffffffu, mx, off));
        float e0 = __expf(v0 - mx);
        float e1 = __expf(v1 - mx);
        float s = e0 + e1;
#pragma unroll
        for (int off = 16; off; off >>= 1)
            s += __shfl_xor_sync(0xffffffffu, s, off);
        float inv = 1.f / s;
        dst[l]      = e0 * inv;
        dst[l + 32] = e1 * inv;
    }
    __syncthreads();

    // --- phase 6: new_A / new_B (4-way k partials; B fp32 from sB) ---
    {
        const int d = tid & 127;
        const int q = tid >> 7;            // k range [16q, 16q+16)
        float na = 0.f, nb = 0.f;
        const float* gA = g_A + (q * 16) * D_DIM + d;
        const float* sb = sB + (q * 16) * PAD_STRIDE + d;
#pragma unroll
        for (int k = 0; k < 16; k++) {
            na = fmaf(rows_w[q * 16 + k], __ldg(gA + k * D_DIM), na);
            nb = fmaf(cols_w[q * 16 + k], sb[k * PAD_STRIDE], nb);
        }
        sAM[tid]       = na;               // sAM free after sim
        sAM[512 + tid] = nb;
    }
    __syncthreads();
    if (tid < D_DIM) {
        newA[tid] = sAM[tid] + sAM[128 + tid] + sAM[256 + tid] + sAM[384 + tid];
        newB[tid] = sAM[512 + tid] + sAM[640 + tid] + sAM[768 + tid] + sAM[896 + tid];
    }
    __syncthreads();

    // --- phase 7: con = newA @ W @ newB + b (4-way d partials) ---
    {
        const int e = tid & 127;
        const int q = tid >> 7;
        const float* wp = W + (q * 32) * D_DIM + e;
        const float* ap = newA + q * 32;
        float s1 = 0.f;
#pragma unroll
        for (int d = 0; d < 32; d++)
            s1 = fmaf(ap[d], wp[d * D_DIM], s1);
        sAM[tid] = s1;
    }
    __syncthreads();
    if (tid < D_DIM) {
        float s1 = sAM[tid] + sAM[128 + tid] + sAM[256 + tid] + sAM[384 + tid];
        float pc = s1 * newB[tid];
#pragma unroll
        for (int off = 16; off; off >>= 1)
            pc += __shfl_down_sync(0xffffffffu, pc, off);
        if (lane == 0) atomicAdd(&scal[3], pc);
    }
    __syncthreads();

    if (tid == 0) {
        float n1 = fmaxf(sqrtf(scal[1]), EPS);
        float n2 = fmaxf(sqrtf(scal[2]), EPS);
        float str_score = scal[0] / (n1 * n2);
        float con_score = scal[3] + b_bi[0];
        out[c] = 0.5f * str_score + 0.5f * con_score;
    }
}

// ---------------------------------------------------------------------------
extern "C" void kernel_launch(void* const* d_in, const int* in_sizes, int n_in,
                              void* d_out, int out_size) {
    const float* table   = (const float*)d_in[0];
    const float* str_t1  = (const float*)d_in[1];
    const float* str_t2s = (const float*)d_in[2];
    const float* att_mat = (const float*)d_in[3];
    const float* W_bi    = (const float*)d_in[4];
    const float* b_bi    = (const float*)d_in[5];
    const int*   t1_ctx  = (const int*)d_in[6];
    const int*   t2_ctx  = (const int*)d_in[7];
    float* out = (float*)d_out;

    cudaFuncSetAttribute(cand_kernel,
                         cudaFuncAttributeMaxDynamicSharedMemorySize,
                         SMEM_FLOATS * sizeof(float));

    prep_kernel<<<K_CTX, 512>>>(table, att_mat, t1_ctx);
    cand_kernel<<<C_CAND, 512, SMEM_FLOATS * sizeof(float)>>>(
        table, str_t1, str_t2s, W_bi, b_bi, t2_ctx, out);
}

// round 15
// speedup vs baseline: 1.8615x; 1.0176x over previous
#include <cuda_runtime.h>
#include <math.h>
#include <stdint.h>

#define K_CTX 64
#define D_DIM 128
#define C_CAND 256
#define DS 200
#define EPS 1e-8f

// Padded row stride: 132 floats (528B, 16B-aligned). Fragment loads at
// word (row*132 + col) -> bank (row*4+col)%32: conflict-free for all frags.
#define PAD_STRIDE 132
#define ROW_BYTES (PAD_STRIDE * 4)      // 528
#define AM_FLOATS (K_CTX * PAD_STRIDE)  // 8448

// Scratch (device globals)
__device__ __align__(16) float g_AM[AM_FLOATS];         // padded, tf32-rounded
__device__ __align__(16) float g_AW[K_CTX * D_DIM];     // A @ W, flat fp32

// smem: sAM(8448) sB(8448) rowP(256) colP(256) rows_w(64) cols_w(64)
//       scal(4) mbars(4)   (sAM doubles as tail scratch)
#define SMEM_FLOATS (AM_FLOATS + AM_FLOATS + 256 + 256 + 64 + 64 + 4 + 4)

__device__ __forceinline__ uint32_t smem_u32(const void* p) {
    return (uint32_t)__cvta_generic_to_shared(p);
}
__device__ __forceinline__ void mbar_init(uint32_t mbar, uint32_t cnt) {
    asm volatile("mbarrier.init.shared.b64 [%0], %1;" :: "r"(mbar), "r"(cnt) : "memory");
}
__device__ __forceinline__ void mbar_expect_tx(uint32_t mbar, uint32_t bytes) {
    asm volatile("mbarrier.arrive.expect_tx.shared.b64 _, [%0], %1;"
                 :: "r"(mbar), "r"(bytes) : "memory");
}
__device__ __forceinline__ void mbar_wait(uint32_t mbar, uint32_t parity) {
    uint32_t done;
    asm volatile(
        "{\n\t.reg .pred p;\n\t"
        "mbarrier.try_wait.parity.acquire.cta.shared::cta.b64 p, [%1], %2;\n\t"
        "selp.b32 %0, 1, 0, p;\n\t}"
        : "=r"(done) : "r"(mbar), "r"(parity) : "memory");
    if (!done) {
        asm volatile(
            "{\n\t.reg .pred P1;\n\t"
            "WAIT_LOOP_%=:\n\t"
            "mbarrier.try_wait.parity.acquire.cta.shared::cta.b64 P1, [%0], %1, 0x989680;\n\t"
            "@P1 bra.uni WAIT_DONE_%=;\n\t"
            "bra.uni WAIT_LOOP_%=;\n\t"
            "WAIT_DONE_%=:\n\t}"
            :: "r"(mbar), "r"(parity) : "memory");
    }
}
__device__ __forceinline__ void bulk_g2s(uint32_t dst_smem, const void* src_gmem,
                                         uint32_t bytes, uint32_t mbar) {
    asm volatile(
        "cp.async.bulk.shared::cluster.global.mbarrier::complete_tx::bytes "
        "[%0], [%1], %2, [%3];"
        :: "r"(dst_smem), "l"(src_gmem), "r"(bytes), "r"(mbar) : "memory");
}
__device__ __forceinline__ float tanh_fast(float x) {
    float y;
    asm("tanh.approx.f32 %0, %1;" : "=f"(y) : "f"(x));
    return y;
}
__device__ __forceinline__ uint32_t to_tf32(float x) {
    uint32_t y;
    asm("cvt.rna.tf32.f32 %0, %1;" : "=r"(y) : "f"(x));
    return y;
}
// m16n8k8 tf32 MMA, fp32 accumulate
__device__ __forceinline__ void mma_tf32(float* c, uint32_t a0, uint32_t a1,
                                         uint32_t a2, uint32_t a3,
                                         uint32_t b0, uint32_t b1) {
    asm volatile(
        "mma.sync.aligned.m16n8k8.row.col.f32.tf32.tf32.f32 "
        "{%0,%1,%2,%3}, {%4,%5,%6,%7}, {%8,%9}, {%0,%1,%2,%3};"
        : "+f"(c[0]), "+f"(c[1]), "+f"(c[2]), "+f"(c[3])
        : "r"(a0), "r"(a1), "r"(a2), "r"(a3), "r"(b0), "r"(b1));
}

// ---------------------------------------------------------------------------
// Kernel 1: prep — grid 64, block 512. Block k computes:
//   g_AM row k = (A @ att_mat) row, padded stride 132, tf32-rounded (MMA A);
//   g_AW row k = (A @ W_bi)    row, flat fp32 (bilinear fold).
// ---------------------------------------------------------------------------
__global__ __launch_bounds__(512, 2)
void prep_kernel(const float* __restrict__ table,
                 const float* __restrict__ att_mat,
                 const float* __restrict__ W,      // W_bi[0]
                 const int* __restrict__ t1_ctx) {
    __shared__ float arow[D_DIM];
    __shared__ float part[512];
    __shared__ float part2[512];
    const int k   = blockIdx.x;
    const int tid = threadIdx.x;

    if (tid < D_DIM)
        arow[tid] = table[(long long)t1_ctx[k] * D_DIM + tid];
    __syncthreads();
    {
        const int d = tid & 127;
        const int q = tid >> 7;
        const float* att = att_mat + (q * 32) * D_DIM + d;
        const float* wp  = W + (q * 32) * D_DIM + d;
        const float* ar  = arow + q * 32;
        float acc = 0.f, acw = 0.f;
#pragma unroll
        for (int e = 0; e < 32; e++) {
            float a = ar[e];
            acc = fmaf(a, att[e * D_DIM], acc);
            acw = fmaf(a, wp[e * D_DIM], acw);
        }
        part[tid]  = acc;
        part2[tid] = acw;
    }
    __syncthreads();
    if (tid < D_DIM) {
        float vm = part[tid] + part[D_DIM + tid]
                 + part[2 * D_DIM + tid] + part[3 * D_DIM + tid];
        float vw = part2[tid] + part2[D_DIM + tid]
                 + part2[2 * D_DIM + tid] + part2[3 * D_DIM + tid];
        g_AM[k * PAD_STRIDE + tid] = __uint_as_float(to_tf32(vm));
        g_AW[k * D_DIM + tid] = vw;
    }
}

// ---------------------------------------------------------------------------
// Kernel 2: main — grid 256, block 512, 3/SM. sim via tf32 MMA; bilinear
// folded through g_AW (no W reads, no newA).
// ---------------------------------------------------------------------------
__global__ __launch_bounds__(512, 3)
void cand_kernel(const float* __restrict__ table,
                 const float* __restrict__ str_t1,
                 const float* __restrict__ str_t2s,
                 const float* __restrict__ b_bi,
                 const int* __restrict__ t2_ctx,
                 float* __restrict__ out) {
    extern __shared__ __align__(16) float sm[];
    float* sAM    = sm;                        // [64][132] tf32 AM (+scratch)
    float* sB     = sAM + AM_FLOATS;           // [64][132] fp32 B
    float* rowP   = sB + AM_FLOATS;            // [4][64]
    float* colP   = rowP + 256;                // [4][64]
    float* rows_w = colP + 256;                // 64
    float* cols_w = rows_w + K_CTX;            // 64
    float* scal   = cols_w + K_CTX;            // 4
    uint64_t* mbars = (uint64_t*)(scal + 4);   // [0]=gather, [1]=AM stage

    const int c    = blockIdx.x;
    const int tid  = threadIdx.x;
    const int wid  = tid >> 5;
    const int lane = tid & 31;
    const uint32_t mbar_g = smem_u32(&mbars[0]);
    const uint32_t mbar_a = smem_u32(&mbars[1]);

    // --- phase 0: init mbarriers + zero accumulators ---
    if (tid == 0) {
        mbar_init(mbar_g, 1);
        mbar_init(mbar_a, 1);
        mbar_expect_tx(mbar_g, K_CTX * D_DIM * 4);
        mbar_expect_tx(mbar_a, AM_FLOATS * 4);
    }
    if (tid < 4) scal[tid] = 0.f;
    __syncthreads();

    // --- phase 1: issue all async copies (graph edge guarantees g_AM) ---
    const int* ctx = t2_ctx + c * K_CTX;
    if (tid < K_CTX) {
        bulk_g2s(smem_u32(sB) + tid * ROW_BYTES,
                 table + (long long)ctx[tid] * D_DIM,
                 D_DIM * 4, mbar_g);
    } else if (tid == K_CTX) {
        bulk_g2s(smem_u32(sAM), g_AM, AM_FLOATS * 4, mbar_a);
    }

    // --- phase 2: string cosine partials ---
    {
        float pd = 0.f, p1 = 0.f, p2 = 0.f;
        if (tid < DS) {
            float x1 = str_t1[tid];
            float x2 = str_t2s[c * DS + tid];
            pd = x1 * x2; p1 = x1 * x1; p2 = x2 * x2;
        }
#pragma unroll
        for (int off = 16; off; off >>= 1) {
            pd += __shfl_down_sync(0xffffffffu, pd, off);
            p1 += __shfl_down_sync(0xffffffffu, p1, off);
            p2 += __shfl_down_sync(0xffffffffu, p2, off);
        }
        if (lane == 0 && wid < 7) {
            atomicAdd(&scal[0], pd);
            atomicAdd(&scal[1], p1);
            atomicAdd(&scal[2], p2);
        }
    }

    // --- phase 3: wait transfers ---
    mbar_wait(mbar_g, 0);
    mbar_wait(mbar_a, 0);
    __syncthreads();

    // --- phase 4: sim = tanh(AM @ B^T) via m16n8k8 tf32 MMA ---
    // warp w: M-tile mt = w&3 (k rows 16mt..+15), N-group g = w>>2 (m cols 16g..+15)
    {
        const int mt = wid & 3;
        const int g  = wid >> 2;
        const int q  = lane >> 2;   // 0..7
        const int r  = lane & 3;    // 0..3
        const float* Ab  = sAM + mt * 16 * PAD_STRIDE;
        const float* Bb0 = sB + (g * 16) * PAD_STRIDE;
        const float* Bb1 = Bb0 + 8 * PAD_STRIDE;

        float c0[4] = {0.f, 0.f, 0.f, 0.f};
        float c1[4] = {0.f, 0.f, 0.f, 0.f};

#pragma unroll
        for (int ks = 0; ks < 16; ks++) {
            const int kb = ks * 8;
            uint32_t a0 = __float_as_uint(Ab[q * PAD_STRIDE + kb + r]);
            uint32_t a1 = __float_as_uint(Ab[(q + 8) * PAD_STRIDE + kb + r]);
            uint32_t a2 = __float_as_uint(Ab[q * PAD_STRIDE + kb + r + 4]);
            uint32_t a3 = __float_as_uint(Ab[(q + 8) * PAD_STRIDE + kb + r + 4]);
            uint32_t b00 = to_tf32(Bb0[q * PAD_STRIDE + kb + r]);
            uint32_t b01 = to_tf32(Bb0[q * PAD_STRIDE + kb + r + 4]);
            uint32_t b10 = to_tf32(Bb1[q * PAD_STRIDE + kb + r]);
            uint32_t b11 = to_tf32(Bb1[q * PAD_STRIDE + kb + r + 4]);

            mma_tf32(c0, a0, a1, a2, a3, b00, b01);
            mma_tf32(c1, a0, a1, a2, a3, b10, b11);
        }

        float d00 = tanh_fast(c0[0]), d01 = tanh_fast(c0[1]);
        float d02 = tanh_fast(c0[2]), d03 = tanh_fast(c0[3]);
        float e00 = tanh_fast(c1[0]), e01 = tanh_fast(c1[1]);
        float e02 = tanh_fast(c1[2]), e03 = tanh_fast(c1[3]);

        // row partials: reduce over r (lane bits 0-1)
        float rp1 = d00 + d01 + e00 + e01;   // row 16mt+q
        float rp2 = d02 + d03 + e02 + e03;   // row 16mt+q+8
#pragma unroll
        for (int off = 1; off <= 2; off <<= 1) {
            rp1 += __shfl_xor_sync(0xffffffffu, rp1, off);
            rp2 += __shfl_xor_sync(0xffffffffu, rp2, off);
        }
        if (r == 0) {
            rowP[g * 64 + mt * 16 + q]     = rp1;
            rowP[g * 64 + mt * 16 + q + 8] = rp2;
        }

        // col partials: reduce over q (lane bits 2-4)
        float cp0 = d00 + d02;
        float cp1 = d01 + d03;
        float cp2 = e00 + e02;
        float cp3 = e01 + e03;
#pragma unroll
        for (int off = 4; off <= 16; off <<= 1) {
            cp0 += __shfl_xor_sync(0xffffffffu, cp0, off);
            cp1 += __shfl_xor_sync(0xffffffffu, cp1, off);
            cp2 += __shfl_xor_sync(0xffffffffu, cp2, off);
            cp3 += __shfl_xor_sync(0xffffffffu, cp3, off);
        }
        if (q == 0) {
            colP[mt * 64 + g * 16 + 2 * r]         = cp0;
            colP[mt * 64 + g * 16 + 2 * r + 1]     = cp1;
            colP[mt * 64 + g * 16 + 8 + 2 * r]     = cp2;
            colP[mt * 64 + g * 16 + 8 + 2 * r + 1] = cp3;
        }
    }
    __syncthreads();

    // --- phase 5: softmax over 64 (warp 0 rows, warp 1 cols; fold partials)
    if (tid < 64) {
        int l = tid & 31;
        const float* P = (tid < 32) ? rowP : colP;
        float* dst     = (tid < 32) ? rows_w : cols_w;
        float v0 = P[l]      + P[64 + l]      + P[128 + l]      + P[192 + l];
        float v1 = P[l + 32] + P[64 + l + 32] + P[128 + l + 32] + P[192 + l + 32];
        v0 *= (1.f / 64.f);
        v1 *= (1.f / 64.f);
        float mx = fmaxf(v0, v1);
#pragma unroll
        for (int off = 16; off; off >>= 1)
            mx = fmaxf(mx, __shfl_xor_sync(0xffffffffu, mx, off));
        float e0 = __expf(v0 - mx);
        float e1 = __expf(v1 - mx);
        float s = e0 + e1;
#pragma unroll
        for (int off = 16; off; off >>= 1)
            s += __shfl_xor_sync(0xffffffffu, s, off);
        float inv = 1.f / s;
        dst[l]      = e0 * inv;
        dst[l + 32] = e1 * inv;
    }
    __syncthreads();

    // --- phase 6: s1 = rows_w @ AW (gmem L2-hot), newB = cols_w @ B (smem);
    //     con = s1 . newB. 4-way k split, single reduction round.
    {
        const int d = tid & 127;
        const int q = tid >> 7;            // k range [16q, 16q+16)
        float s1p = 0.f, nbp = 0.f;
        const float* gW = g_AW + (q * 16) * D_DIM + d;
        const float* sb = sB + (q * 16) * PAD_STRIDE + d;
#pragma unroll
        for (int k = 0; k < 16; k++) {
            s1p = fmaf(rows_w[q * 16 + k], __ldg(gW + k * D_DIM), s1p);
            nbp = fmaf(cols_w[q * 16 + k], sb[k * PAD_STRIDE], nbp);
        }
        sAM[tid]       = s1p;              // sAM free after sim
        sAM[512 + tid] = nbp;
    }
    __syncthreads();
    if (tid < D_DIM) {
        float s1 = sAM[tid] + sAM[128 + tid] + sAM[256 + tid] + sAM[384 + tid];
        float nb = sAM[512 + tid] + sAM[640 + tid] + sAM[768 + tid] + sAM[896 + tid];
        float pc = s1 * nb;
#pragma unroll
        for (int off = 16; off; off >>= 1)
            pc += __shfl_down_sync(0xffffffffu, pc, off);
        if (lane == 0) atomicAdd(&scal[3], pc);
    }
    __syncthreads();

    if (tid == 0) {
        float n1 = fmaxf(sqrtf(scal[1]), EPS);
        float n2 = fmaxf(sqrtf(scal[2]), EPS);
        float str_score = scal[0] / (n1 * n2);
        float con_score = scal[3] + b_bi[0];
        out[c] = 0.5f * str_score + 0.5f * con_score;
    }
}

// ---------------------------------------------------------------------------
extern "C" void kernel_launch(void* const* d_in, const int* in_sizes, int n_in,
                              void* d_out, int out_size) {
    const float* table   = (const float*)d_in[0];
    const float* str_t1  = (const float*)d_in[1];
    const float* str_t2s = (const float*)d_in[2];
    const float* att_mat = (const float*)d_in[3];
    const float* W_bi    = (const float*)d_in[4];
    const float* b_bi    = (const float*)d_in[5];
    const int*   t1_ctx  = (const int*)d_in[6];
    const int*   t2_ctx  = (const int*)d_in[7];
    float* out = (float*)d_out;

    cudaFuncSetAttribute(cand_kernel,
                         cudaFuncAttributeMaxDynamicSharedMemorySize,
                         SMEM_FLOATS * sizeof(float));

    prep_kernel<<<K_CTX, 512>>>(table, att_mat, W_bi, t1_ctx);
    cand_kernel<<<C_CAND, 512, SMEM_FLOATS * sizeof(float)>>>(
        table, str_t1, str_t2s, b_bi, t2_ctx, out);
}